// round 8
// baseline (speedup 1.0000x reference)
#include <cuda_runtime.h>
#include <cuda_fp16.h>
#include <cstdint>

// ============================================================
// BinaryMLP fused kernel (sm_103 virtual arch — portable mma.sync).
// R8 (= R7 minus the device-lambda, which the harness nvcc rejects):
// N-split layers (D = 64 regs instead of 128) + warp-private
// 13-slot smem ring for ALL activations (thread-private, no sync).
// 12 warps/CTA (occ 18.75%, 3 warps/SMSP) vs R6's 8 @ 246 regs.
// 32 rows/warp, fp16 single-pass, sign-byte weights + PRMT expand.
// ============================================================

#define DIN   196
#define KPAD  208
#define HID   128
#define DOUT  10
#define NWARP 12
#define CTA_THREADS (NWARP * 32)

// ---- smem layout ----
#define SM_W1S  0                        // 13*4*512 = 26624
#define SM_W2S  (SM_W1S + 13*4*512)
#define SM_W3S  (SM_W2S + 8*4*512)
#define SM_W4HF (SM_W3S + 8*4*512)       // [8][16]*32 = 4096
#define SM_W4LF (SM_W4HF + 8*16*32)
#define SM_B1   (SM_W4LF + 8*16*32)
#define SM_B2   (SM_B1 + 512)
#define SM_B3   (SM_B2 + 512)
#define SM_B4   (SM_B3 + 512)
#define SM_SCR  (SM_B4 + 512)            // ring scratch: NWARP * 13 * 1024
#define SCR_PER_WARP (13 * 1024)
#define SM_TOTAL (SM_SCR + NWARP * SCR_PER_WARP)   // 69632 + 159744 = 229376

__device__ __forceinline__ int frag_off(int k) {
    return ((k & 7) >> 1) * 8 + ((k >> 3) & 1) * 4 + (k & 1) * 2;
}
__device__ __forceinline__ int sgn_addr(int n, int k) {
    int kk = k >> 4, nb = n >> 3, ng = nb >> 2, j = nb & 3;
    return ((kk * 4 + ng) << 9) + (((n & 7) * 4 + ((k & 7) >> 1)) << 4)
         + (j << 2) + (((k >> 3) & 1) << 1) + (k & 1);
}

__device__ __forceinline__ void mma16816(float* d, const uint32_t* a, const uint32_t* b) {
    asm volatile(
        "mma.sync.aligned.m16n8k16.row.col.f32.f16.f16.f32 "
        "{%0,%1,%2,%3},{%4,%5,%6,%7},{%8,%9},{%0,%1,%2,%3};"
        : "+f"(d[0]), "+f"(d[1]), "+f"(d[2]), "+f"(d[3])
        : "r"(a[0]), "r"(a[1]), "r"(a[2]), "r"(a[3]), "r"(b[0]), "r"(b[1]));
}

__device__ __forceinline__ uint32_t h2pack(float a, float b) {
    __half2 h = __floats2half2_rn(a, b);
    return *reinterpret_cast<uint32_t*>(&h);
}

// one n-half epilogue (4 kk' slots) -> smem ring
template<class EFN>
__device__ __forceinline__ void epi_to_smem(
    const float D0[8][4], const float D1[8][4], const float* bias_h, int q,
    char* scr, int h, EFN eslot)
{
    #pragma unroll
    for (int j = 0; j < 4; j++) {
        const float* bp = bias_h + 16 * j + q * 2;
        float2 b0 = *(const float2*)bp;
        float2 b1 = *(const float2*)(bp + 8);
        int f0 = 2 * j, f1 = f0 + 1;
        uint32_t w0 = h2pack(fmaxf(D0[f0][0] + b0.x, 0.f), fmaxf(D0[f0][1] + b0.y, 0.f));
        uint32_t w1 = h2pack(fmaxf(D0[f0][2] + b0.x, 0.f), fmaxf(D0[f0][3] + b0.y, 0.f));
        uint32_t w2 = h2pack(fmaxf(D0[f1][0] + b1.x, 0.f), fmaxf(D0[f1][1] + b1.y, 0.f));
        uint32_t w3 = h2pack(fmaxf(D0[f1][2] + b1.x, 0.f), fmaxf(D0[f1][3] + b1.y, 0.f));
        uint32_t v0 = h2pack(fmaxf(D1[f0][0] + b0.x, 0.f), fmaxf(D1[f0][1] + b0.y, 0.f));
        uint32_t v1 = h2pack(fmaxf(D1[f0][2] + b0.x, 0.f), fmaxf(D1[f0][3] + b0.y, 0.f));
        uint32_t v2 = h2pack(fmaxf(D1[f1][0] + b1.x, 0.f), fmaxf(D1[f1][1] + b1.y, 0.f));
        uint32_t v3 = h2pack(fmaxf(D1[f1][2] + b1.x, 0.f), fmaxf(D1[f1][3] + b1.y, 0.f));
        int es = eslot(h, j);
        *(uint4*)(scr + es * 1024)       = make_uint4(w0, w1, w2, w3);
        *(uint4*)(scr + es * 1024 + 512) = make_uint4(v0, v1, v2, v3);
    }
}

// hidden layer (L2/L3): 8 kk slots, N split into two halves
template<class SFN, class EFN>
__device__ __forceinline__ void hidden_layer(
    char* scr, const char* Ws_lane, const float* bias, int q,
    SFN slot_of, EFN eslot)
{
    float D0[8][4], D1[8][4];
    #pragma unroll
    for (int h = 0; h < 2; h++) {
        #pragma unroll
        for (int f = 0; f < 8; f++)
            #pragma unroll
            for (int j = 0; j < 4; j++) { D0[f][j] = 0.f; D1[f][j] = 0.f; }
        #pragma unroll
        for (int kk = 0; kk < 8; kk++) {
            int s = slot_of(kk);
            uint4 av0 = *(const uint4*)(scr + s * 1024);
            uint4 av1 = *(const uint4*)(scr + s * 1024 + 512);
            uint32_t a0[4] = { av0.x, av0.y, av0.z, av0.w };
            uint32_t a1[4] = { av1.x, av1.y, av1.z, av1.w };
            #pragma unroll
            for (int g = 0; g < 2; g++) {
                int ng = 2 * h + g;
                uint4 w = *(const uint4*)(Ws_lane + ((kk * 4 + ng) << 9));
                uint32_t bw0[2] = { __byte_perm(w.x, 0, 0x1404), __byte_perm(w.x, 0, 0x3424) };
                uint32_t bw1[2] = { __byte_perm(w.y, 0, 0x1404), __byte_perm(w.y, 0, 0x3424) };
                uint32_t bw2[2] = { __byte_perm(w.z, 0, 0x1404), __byte_perm(w.z, 0, 0x3424) };
                uint32_t bw3[2] = { __byte_perm(w.w, 0, 0x1404), __byte_perm(w.w, 0, 0x3424) };
                mma16816(D0[g * 4 + 0], a0, bw0); mma16816(D1[g * 4 + 0], a1, bw0);
                mma16816(D0[g * 4 + 1], a0, bw1); mma16816(D1[g * 4 + 1], a1, bw1);
                mma16816(D0[g * 4 + 2], a0, bw2); mma16816(D1[g * 4 + 2], a1, bw2);
                mma16816(D0[g * 4 + 3], a0, bw3); mma16816(D1[g * 4 + 3], a1, bw3);
            }
        }
        epi_to_smem(D0, D1, bias + 64 * h, q, scr, h, eslot);
    }
}

struct SlotL2 { __device__ __forceinline__ int operator()(int kk) const { return kk; } };
struct EpiL2  { __device__ __forceinline__ int operator()(int h, int j) const { return h ? j : 8 + j; } };
struct SlotL3 { __device__ __forceinline__ int operator()(int kk) const { return kk < 4 ? kk + 8 : kk - 4; } };
struct EpiL3  { __device__ __forceinline__ int operator()(int h, int j) const { return h ? 8 + j : 4 + j; } };
struct EpiL1H1 { __device__ __forceinline__ int operator()(int, int j) const { return 4 + j; } };

__global__ void __launch_bounds__(CTA_THREADS, 1) bmlp_kernel(
    const float* __restrict__ x,
    const float* __restrict__ W1, const float* __restrict__ b1,
    const float* __restrict__ W2, const float* __restrict__ b2,
    const float* __restrict__ W3, const float* __restrict__ b3,
    const float* __restrict__ W4, const float* __restrict__ b4,
    float* __restrict__ out, int n_units)
{
    extern __shared__ char smem[];
    const int tid = threadIdx.x;
    const int lane = tid & 31;
    const int warp = tid >> 5;
    const int r = lane >> 2;
    const int q = lane & 3;

    // ---------------- prologue: weights -> smem ----------------
    for (int i = tid; i < HID * KPAD; i += CTA_THREADS) {
        int n = i / KPAD, k = i - n * KPAD;
        unsigned char s = 0;
        if (k < DIN) {
            float w = W1[n * DIN + k];
            s = (w > 0.f) ? 0x3Cu : ((w < 0.f) ? 0xBCu : 0u);
        }
        smem[SM_W1S + sgn_addr(n, k)] = s;
    }
    for (int i = tid; i < HID * HID; i += CTA_THREADS) {
        int n = i >> 7, k = i & 127;
        float w2 = W2[i], w3 = W3[i];
        unsigned char s2 = (w2 > 0.f) ? 0x3Cu : ((w2 < 0.f) ? 0xBCu : 0u);
        unsigned char s3 = (w3 > 0.f) ? 0x3Cu : ((w3 < 0.f) ? 0xBCu : 0u);
        int a = sgn_addr(n, k);
        smem[SM_W2S + a] = s2;
        smem[SM_W3S + a] = s3;
    }
    for (int i = tid; i < 16 * HID; i += CTA_THREADS) {
        int n = i >> 7, k = i & 127;
        float w = (n < DOUT) ? W4[n * HID + k] : 0.f;
        __half h = __float2half_rn(w);
        __half l = __float2half_rn(w - __half2float(h));
        int ofs = ((k >> 4) * 16 + n) * 32 + frag_off(k);
        *(unsigned short*)(smem + SM_W4HF + ofs) = __half_as_ushort(h);
        *(unsigned short*)(smem + SM_W4LF + ofs) = __half_as_ushort(l);
    }
    if (tid < HID) {
        ((float*)(smem + SM_B1))[tid] = b1[tid];
        ((float*)(smem + SM_B2))[tid] = b2[tid];
        ((float*)(smem + SM_B3))[tid] = b3[tid];
    }
    if (tid < 16) ((float*)(smem + SM_B4))[tid] = (tid < DOUT) ? b4[tid] : 0.f;
    __syncthreads();
    // Zero barriers after this point.

    const float* b1s = (const float*)(smem + SM_B1);
    const float* b2s = (const float*)(smem + SM_B2);
    const float* b3s = (const float*)(smem + SM_B3);
    const float* b4s = (const float*)(smem + SM_B4);
    const char* w1p = smem + SM_W1S + lane * 16;
    const char* w2p = smem + SM_W2S + lane * 16;
    const char* w3p = smem + SM_W3S + lane * 16;
    char* scr = smem + SM_SCR + warp * SCR_PER_WARP + lane * 16;

    const int wstride = gridDim.x * NWARP;
    for (int c = blockIdx.x * NWARP + warp; c < n_units; c += wstride) {
        const size_t row0 = (size_t)c * 32 + r;
        const float* xa = x + row0 * DIN;
        const float* xb = xa + (size_t)8 * DIN;
        const float* xc = xa + (size_t)16 * DIN;
        const float* xd = xa + (size_t)24 * DIN;

        // ================= layer 1 =================
        {
            float D0[8][4], D1[8][4];
            uint32_t T0[4][4], T1[4][4];     // h0 epilogue buffered in regs

            // ---- h = 0: LDG + stage to ring slots 0..12, MMA ng 0,1 ----
            #pragma unroll
            for (int f = 0; f < 8; f++)
                #pragma unroll
                for (int j = 0; j < 4; j++) { D0[f][j] = 0.f; D1[f][j] = 0.f; }
            #pragma unroll
            for (int kk = 0; kk < 13; kk++) {
                int c0 = kk * 16 + q * 2;
                int c1 = c0 + 8;
                float2 z = make_float2(0.f, 0.f);
                float2 pa0 = (c0 < DIN) ? *(const float2*)(xa + c0) : z;
                float2 pb0 = (c0 < DIN) ? *(const float2*)(xb + c0) : z;
                float2 pc0 = (c0 < DIN) ? *(const float2*)(xc + c0) : z;
                float2 pd0 = (c0 < DIN) ? *(const float2*)(xd + c0) : z;
                float2 pa1 = (c1 < DIN) ? *(const float2*)(xa + c1) : z;
                float2 pb1 = (c1 < DIN) ? *(const float2*)(xb + c1) : z;
                float2 pc1 = (c1 < DIN) ? *(const float2*)(xc + c1) : z;
                float2 pd1 = (c1 < DIN) ? *(const float2*)(xd + c1) : z;
                uint32_t a0[4], a1[4];
                a0[0] = h2pack(pa0.x, pa0.y); a0[1] = h2pack(pb0.x, pb0.y);
                a0[2] = h2pack(pa1.x, pa1.y); a0[3] = h2pack(pb1.x, pb1.y);
                a1[0] = h2pack(pc0.x, pc0.y); a1[1] = h2pack(pd0.x, pd0.y);
                a1[2] = h2pack(pc1.x, pc1.y); a1[3] = h2pack(pd1.x, pd1.y);
                *(uint4*)(scr + kk * 1024)       = make_uint4(a0[0], a0[1], a0[2], a0[3]);
                *(uint4*)(scr + kk * 1024 + 512) = make_uint4(a1[0], a1[1], a1[2], a1[3]);
                #pragma unroll
                for (int g = 0; g < 2; g++) {
                    uint4 w = *(const uint4*)(w1p + ((kk * 4 + g) << 9));
                    uint32_t bw0[2] = { __byte_perm(w.x, 0, 0x1404), __byte_perm(w.x, 0, 0x3424) };
                    uint32_t bw1[2] = { __byte_perm(w.y, 0, 0x1404), __byte_perm(w.y, 0, 0x3424) };
                    uint32_t bw2[2] = { __byte_perm(w.z, 0, 0x1404), __byte_perm(w.z, 0, 0x3424) };
                    uint32_t bw3[2] = { __byte_perm(w.w, 0, 0x1404), __byte_perm(w.w, 0, 0x3424) };
                    mma16816(D0[g * 4 + 0], a0, bw0); mma16816(D1[g * 4 + 0], a1, bw0);
                    mma16816(D0[g * 4 + 1], a0, bw1); mma16816(D1[g * 4 + 1], a1, bw1);
                    mma16816(D0[g * 4 + 2], a0, bw2); mma16816(D1[g * 4 + 2], a1, bw2);
                    mma16816(D0[g * 4 + 3], a0, bw3); mma16816(D1[g * 4 + 3], a1, bw3);
                }
            }
            // h0 epilogue -> registers (slots 0..3 still live for h1)
            #pragma unroll
            for (int j = 0; j < 4; j++) {
                const float* bp = b1s + 16 * j + q * 2;
                float2 b0 = *(const float2*)bp;
                float2 b1v = *(const float2*)(bp + 8);
                int f0 = 2 * j, f1 = f0 + 1;
                T0[j][0] = h2pack(fmaxf(D0[f0][0] + b0.x, 0.f), fmaxf(D0[f0][1] + b0.y, 0.f));
                T0[j][1] = h2pack(fmaxf(D0[f0][2] + b0.x, 0.f), fmaxf(D0[f0][3] + b0.y, 0.f));
                T0[j][2] = h2pack(fmaxf(D0[f1][0] + b1v.x, 0.f), fmaxf(D0[f1][1] + b1v.y, 0.f));
                T0[j][3] = h2pack(fmaxf(D0[f1][2] + b1v.x, 0.f), fmaxf(D0[f1][3] + b1v.y, 0.f));
                T1[j][0] = h2pack(fmaxf(D1[f0][0] + b0.x, 0.f), fmaxf(D1[f0][1] + b0.y, 0.f));
                T1[j][1] = h2pack(fmaxf(D1[f0][2] + b0.x, 0.f), fmaxf(D1[f0][3] + b0.y, 0.f));
                T1[j][2] = h2pack(fmaxf(D1[f1][0] + b1v.x, 0.f), fmaxf(D1[f1][1] + b1v.y, 0.f));
                T1[j][3] = h2pack(fmaxf(D1[f1][2] + b1v.x, 0.f), fmaxf(D1[f1][3] + b1v.y, 0.f));
            }

            // ---- h = 1: A from ring, MMA ng 2,3 ----
            #pragma unroll
            for (int f = 0; f < 8; f++)
                #pragma unroll
                for (int j = 0; j < 4; j++) { D0[f][j] = 0.f; D1[f][j] = 0.f; }
            #pragma unroll
            for (int kk = 0; kk < 13; kk++) {
                uint4 av0 = *(const uint4*)(scr + kk * 1024);
                uint4 av1 = *(const uint4*)(scr + kk * 1024 + 512);
                uint32_t a0[4] = { av0.x, av0.y, av0.z, av0.w };
                uint32_t a1[4] = { av1.x, av1.y, av1.z, av1.w };
                #pragma unroll
                for (int g = 0; g < 2; g++) {
                    uint4 w = *(const uint4*)(w1p + ((kk * 4 + 2 + g) << 9));
                    uint32_t bw0[2] = { __byte_perm(w.x, 0, 0x1404), __byte_perm(w.x, 0, 0x3424) };
                    uint32_t bw1[2] = { __byte_perm(w.y, 0, 0x1404), __byte_perm(w.y, 0, 0x3424) };
                    uint32_t bw2[2] = { __byte_perm(w.z, 0, 0x1404), __byte_perm(w.z, 0, 0x3424) };
                    uint32_t bw3[2] = { __byte_perm(w.w, 0, 0x1404), __byte_perm(w.w, 0, 0x3424) };
                    mma16816(D0[g * 4 + 0], a0, bw0); mma16816(D1[g * 4 + 0], a1, bw0);
                    mma16816(D0[g * 4 + 1], a0, bw1); mma16816(D1[g * 4 + 1], a1, bw1);
                    mma16816(D0[g * 4 + 2], a0, bw2); mma16816(D1[g * 4 + 2], a1, bw2);
                    mma16816(D0[g * 4 + 3], a0, bw3); mma16816(D1[g * 4 + 3], a1, bw3);
                }
            }
            // h1 epilogue -> slots 4..7 (L1 slots fully consumed)
            epi_to_smem(D0, D1, b1s + 64, q, scr, 1, EpiL1H1());
            // flush buffered h0 results -> slots 0..3
            #pragma unroll
            for (int j = 0; j < 4; j++) {
                *(uint4*)(scr + j * 1024)       = make_uint4(T0[j][0], T0[j][1], T0[j][2], T0[j][3]);
                *(uint4*)(scr + j * 1024 + 512) = make_uint4(T1[j][0], T1[j][1], T1[j][2], T1[j][3]);
            }
        }

        // ================= layers 2, 3 =================
        hidden_layer(scr, w2p, b2s, q, SlotL2(), EpiL2());
        hidden_layer(scr, w3p, b3s, q, SlotL3(), EpiL3());

        // ================= layer 4 (head; A slots kk+4) =================
        float D4a[2][4], D4b[2][4];
        #pragma unroll
        for (int f = 0; f < 2; f++)
            #pragma unroll
            for (int j = 0; j < 4; j++) { D4a[f][j] = 0.f; D4b[f][j] = 0.f; }
        #pragma unroll
        for (int kk = 0; kk < 8; kk++) {
            int s = kk + 4;
            uint4 av0 = *(const uint4*)(scr + s * 1024);
            uint4 av1 = *(const uint4*)(scr + s * 1024 + 512);
            uint32_t a0[4] = { av0.x, av0.y, av0.z, av0.w };
            uint32_t a1[4] = { av1.x, av1.y, av1.z, av1.w };
            #pragma unroll
            for (int n = 0; n < 2; n++) {
                int ofs = ((kk * 16 + n * 8 + r) << 5) + q * 8;
                uint2 bhw = *(const uint2*)(smem + SM_W4HF + ofs);
                uint2 blw = *(const uint2*)(smem + SM_W4LF + ofs);
                uint32_t bh[2] = { bhw.x, bhw.y };
                uint32_t bl[2] = { blw.x, blw.y };
                mma16816(D4a[n], a0, bh);
                mma16816(D4a[n], a0, bl);
                mma16816(D4b[n], a1, bh);
                mma16816(D4b[n], a1, bl);
            }
        }

        // ---- output, both halves ----
        #pragma unroll
        for (int h = 0; h < 2; h++) {
            const float (*D4)[4] = (h == 0) ? D4a : D4b;
            float* o0 = out + (row0 + h * 16) * DOUT;
            float* o8 = o0 + (size_t)8 * DOUT;
            int cc = q * 2;
            float2 bb = *(const float2*)(b4s + cc);
            *(float2*)(o0 + cc) = make_float2(D4[0][0] + bb.x, D4[0][1] + bb.y);
            *(float2*)(o8 + cc) = make_float2(D4[0][2] + bb.x, D4[0][3] + bb.y);
            if (q == 0) {
                float2 b8 = *(const float2*)(b4s + 8);
                *(float2*)(o0 + 8) = make_float2(D4[1][0] + b8.x, D4[1][1] + b8.y);
                *(float2*)(o8 + 8) = make_float2(D4[1][2] + b8.x, D4[1][3] + b8.y);
            }
        }
    }
}

extern "C" void kernel_launch(void* const* d_in, const int* in_sizes, int n_in,
                              void* d_out, int out_size) {
    const float* x  = (const float*)d_in[0];
    const float* W1 = (const float*)d_in[1];
    const float* b1 = (const float*)d_in[2];
    const float* W2 = (const float*)d_in[3];
    const float* b2 = (const float*)d_in[4];
    const float* W3 = (const float*)d_in[5];
    const float* b3 = (const float*)d_in[6];
    const float* W4 = (const float*)d_in[7];
    const float* b4 = (const float*)d_in[8];
    float* out = (float*)d_out;

    int B = in_sizes[0] / DIN;
    int n_units = B / 32;

    static int configured = 0;
    if (!configured) {
        cudaFuncSetAttribute(bmlp_kernel, cudaFuncAttributeMaxDynamicSharedMemorySize, SM_TOTAL);
        configured = 1;
    }

    int grid = 152;
    int max_grid = (n_units + NWARP - 1) / NWARP;
    if (grid > max_grid) grid = max_grid;
    bmlp_kernel<<<grid, CTA_THREADS, SM_TOTAL>>>(x, W1, b1, W2, b2, W3, b3, W4, b4, out, n_units);
}

// round 10
// speedup vs baseline: 1.3913x; 1.3913x over previous
#include <cuda_runtime.h>
#include <cuda_fp16.h>
#include <cstdint>

// ============================================================
// BinaryMLP fused kernel (sm_103 virtual arch — portable mma.sync).
// R10 = R9 resubmitted after infra failure (container died; no
// kernel signal). 16 rows/warp, 12 warps/CTA, cp.async (LDGSTS)
// prefetch of the next chunk's x into a warp-private smem stage
// buffer (single buffer; prefetch issued after layer-1 consumes,
// waited at loop top). Grouped B loads: 1 LDS.128 per 4 MMAs.
// fp16 single-pass, sign-byte weights + PRMT expansion, zero
// barriers in steady state.
// ============================================================

#define DIN   196
#define HID   128
#define DOUT  10
#define NWARP 12
#define CTA_THREADS (NWARP * 32)
#define XSTRIDE 800                      // bytes per staged row (200 floats, 16B aligned)
#define XBUF_PER_WARP (16 * XSTRIDE)     // 12800 B

// ---- smem layout ----
#define SM_W1S  0                        // 13*4*512 = 26624
#define SM_W2S  (SM_W1S + 13*4*512)
#define SM_W3S  (SM_W2S + 8*4*512)
#define SM_W4HF (SM_W3S + 8*4*512)       // [8][16]*32 = 4096
#define SM_W4LF (SM_W4HF + 8*16*32)
#define SM_B1   (SM_W4LF + 8*16*32)
#define SM_B2   (SM_B1 + 512)
#define SM_B3   (SM_B2 + 512)
#define SM_B4   (SM_B3 + 512)
#define SM_XBUF (SM_B4 + 512)            // 12 * 12800 = 153600
#define SM_TOTAL (SM_XBUF + NWARP * XBUF_PER_WARP)   // 223232

__device__ __forceinline__ int frag_off(int k) {
    return ((k & 7) >> 1) * 8 + ((k >> 3) & 1) * 4 + (k & 1) * 2;
}
__device__ __forceinline__ int sgn_addr(int n, int k) {
    int kk = k >> 4, nb = n >> 3, ng = nb >> 2, j = nb & 3;
    return ((kk * 4 + ng) << 9) + (((n & 7) * 4 + ((k & 7) >> 1)) << 4)
         + (j << 2) + (((k >> 3) & 1) << 1) + (k & 1);
}

__device__ __forceinline__ void mma16816(float* d, const uint32_t* a, const uint32_t* b) {
    asm volatile(
        "mma.sync.aligned.m16n8k16.row.col.f32.f16.f16.f32 "
        "{%0,%1,%2,%3},{%4,%5,%6,%7},{%8,%9},{%0,%1,%2,%3};"
        : "+f"(d[0]), "+f"(d[1]), "+f"(d[2]), "+f"(d[3])
        : "r"(a[0]), "r"(a[1]), "r"(a[2]), "r"(a[3]), "r"(b[0]), "r"(b[1]));
}

__device__ __forceinline__ uint32_t h2pack(float a, float b) {
    __half2 h = __floats2half2_rn(a, b);
    return *reinterpret_cast<uint32_t*>(&h);
}

#define CP_ASYNC16(dst_u32, gptr) \
    asm volatile("cp.async.cg.shared.global [%0], [%1], 16;" :: "r"(dst_u32), "l"(gptr) : "memory")
#define CP_COMMIT() asm volatile("cp.async.commit_group;" ::: "memory")
#define CP_WAIT0()  asm volatile("cp.async.wait_group 0;" ::: "memory")

// D -> +bias, ReLU, fp16 pack -> A fragments for next layer
__device__ __forceinline__ void epilogue_hidden(
    const float D[16][4], const float* bias, int q, uint32_t Ah[8][4])
{
    #pragma unroll
    for (int kk = 0; kk < 8; kk++) {
        const float* bp = bias + 16 * kk + q * 2;
        float2 b0 = *(const float2*)bp;
        float2 b1 = *(const float2*)(bp + 8);
        int f0 = 2 * kk, f1 = f0 + 1;
        Ah[kk][0] = h2pack(fmaxf(D[f0][0] + b0.x, 0.f), fmaxf(D[f0][1] + b0.y, 0.f));
        Ah[kk][1] = h2pack(fmaxf(D[f0][2] + b0.x, 0.f), fmaxf(D[f0][3] + b0.y, 0.f));
        Ah[kk][2] = h2pack(fmaxf(D[f1][0] + b1.x, 0.f), fmaxf(D[f1][1] + b1.y, 0.f));
        Ah[kk][3] = h2pack(fmaxf(D[f1][2] + b1.x, 0.f), fmaxf(D[f1][3] + b1.y, 0.f));
    }
}

__global__ void __launch_bounds__(CTA_THREADS, 1) bmlp_kernel(
    const float* __restrict__ x,
    const float* __restrict__ W1, const float* __restrict__ b1,
    const float* __restrict__ W2, const float* __restrict__ b2,
    const float* __restrict__ W3, const float* __restrict__ b3,
    const float* __restrict__ W4, const float* __restrict__ b4,
    float* __restrict__ out, int n_chunks)
{
    extern __shared__ char smem[];
    const int tid = threadIdx.x;
    const int lane = tid & 31;
    const int warp = tid >> 5;
    const int r = lane >> 2;
    const int q = lane & 3;

    // ---------------- prologue: weights -> smem ----------------
    for (int i = tid; i < HID * 208; i += CTA_THREADS) {
        int n = i / 208, k = i - n * 208;
        unsigned char s = 0;
        if (k < DIN) {
            float w = W1[n * DIN + k];
            s = (w > 0.f) ? 0x3Cu : ((w < 0.f) ? 0xBCu : 0u);
        }
        smem[SM_W1S + sgn_addr(n, k)] = s;
    }
    for (int i = tid; i < HID * HID; i += CTA_THREADS) {
        int n = i >> 7, k = i & 127;
        float w2 = W2[i], w3 = W3[i];
        unsigned char s2 = (w2 > 0.f) ? 0x3Cu : ((w2 < 0.f) ? 0xBCu : 0u);
        unsigned char s3 = (w3 > 0.f) ? 0x3Cu : ((w3 < 0.f) ? 0xBCu : 0u);
        int a = sgn_addr(n, k);
        smem[SM_W2S + a] = s2;
        smem[SM_W3S + a] = s3;
    }
    for (int i = tid; i < 16 * HID; i += CTA_THREADS) {
        int n = i >> 7, k = i & 127;
        float w = (n < DOUT) ? W4[n * HID + k] : 0.f;
        __half h = __float2half_rn(w);
        __half l = __float2half_rn(w - __half2float(h));
        int ofs = ((k >> 4) * 16 + n) * 32 + frag_off(k);
        *(unsigned short*)(smem + SM_W4HF + ofs) = __half_as_ushort(h);
        *(unsigned short*)(smem + SM_W4LF + ofs) = __half_as_ushort(l);
    }
    if (tid < HID) {
        ((float*)(smem + SM_B1))[tid] = b1[tid];
        ((float*)(smem + SM_B2))[tid] = b2[tid];
        ((float*)(smem + SM_B3))[tid] = b3[tid];
    }
    if (tid < 16) ((float*)(smem + SM_B4))[tid] = (tid < DOUT) ? b4[tid] : 0.f;

    // zero the per-row pad (cols 196..199) of this warp's x stage — written once,
    // never touched by cp.async (which copies only 784 B/row)
    char* xbuf = smem + SM_XBUF + warp * XBUF_PER_WARP;
    if (lane < 16)
        *(uint4*)(xbuf + lane * XSTRIDE + 784) = make_uint4(0, 0, 0, 0);
    __syncthreads();
    // Zero barriers after this point: warps fully independent.

    const float* b1s = (const float*)(smem + SM_B1);
    const float* b2s = (const float*)(smem + SM_B2);
    const float* b3s = (const float*)(smem + SM_B3);
    const float* b4s = (const float*)(smem + SM_B4);
    const char* w1p = smem + SM_W1S + lane * 16;
    const char* w2p = smem + SM_W2S + lane * 16;
    const char* w3p = smem + SM_W3S + lane * 16;

    const int wstride = gridDim.x * NWARP;
    const int c_first = blockIdx.x * NWARP + warp;

    // ---- prime the pipeline: prefetch the first chunk ----
    if (c_first < n_chunks) {
        const char* gbase = (const char*)(x + (size_t)c_first * 16 * DIN);
        for (int u = lane; u < 784; u += 32) {
            int row = u / 49, off = (u - row * 49) * 16;
            uint32_t dst = (uint32_t)__cvta_generic_to_shared(xbuf + row * XSTRIDE + off);
            CP_ASYNC16(dst, gbase + row * 784 + off);
        }
    }
    CP_COMMIT();

    for (int c = c_first; c < n_chunks; c += wstride) {
        CP_WAIT0();     // x for chunk c is resident in xbuf

        float D[16][4];
        #pragma unroll
        for (int f = 0; f < 16; f++)
            #pragma unroll
            for (int j = 0; j < 4; j++) D[f][j] = 0.f;

        // ---- layer 1: A from staged x (rows r, r+8), 13 k-steps ----
        #pragma unroll
        for (int kk = 0; kk < 13; kk++) {
            int c0 = kk * 16 + q * 2;           // < 200 always (pad holds zeros)
            uint32_t a[4];
            float2 p0 = *(const float2*)(xbuf + r * XSTRIDE + c0 * 4);
            float2 p1 = *(const float2*)(xbuf + (r + 8) * XSTRIDE + c0 * 4);
            a[0] = h2pack(p0.x, p0.y);
            a[1] = h2pack(p1.x, p1.y);
            if (kk < 12) {
                int c1 = c0 + 8;
                float2 p2 = *(const float2*)(xbuf + r * XSTRIDE + c1 * 4);
                float2 p3 = *(const float2*)(xbuf + (r + 8) * XSTRIDE + c1 * 4);
                a[2] = h2pack(p2.x, p2.y);
                a[3] = h2pack(p3.x, p3.y);
            } else {
                a[2] = 0u; a[3] = 0u;           // cols 200..207 are pure pad
            }
            #pragma unroll
            for (int ng = 0; ng < 4; ng++) {
                uint4 w = *(const uint4*)(w1p + (((kk * 4 + ng) << 9)));
                uint32_t bw0[2] = { __byte_perm(w.x, 0, 0x1404), __byte_perm(w.x, 0, 0x3424) };
                uint32_t bw1[2] = { __byte_perm(w.y, 0, 0x1404), __byte_perm(w.y, 0, 0x3424) };
                uint32_t bw2[2] = { __byte_perm(w.z, 0, 0x1404), __byte_perm(w.z, 0, 0x3424) };
                uint32_t bw3[2] = { __byte_perm(w.w, 0, 0x1404), __byte_perm(w.w, 0, 0x3424) };
                mma16816(D[ng * 4 + 0], a, bw0);
                mma16816(D[ng * 4 + 1], a, bw1);
                mma16816(D[ng * 4 + 2], a, bw2);
                mma16816(D[ng * 4 + 3], a, bw3);
            }
        }

        // ---- prefetch next chunk's x (all layer-1 reads already issued) ----
        {
            int cn = c + wstride;
            if (cn < n_chunks) {
                const char* gbase = (const char*)(x + (size_t)cn * 16 * DIN);
                for (int u = lane; u < 784; u += 32) {
                    int row = u / 49, off = (u - row * 49) * 16;
                    uint32_t dst = (uint32_t)__cvta_generic_to_shared(xbuf + row * XSTRIDE + off);
                    CP_ASYNC16(dst, gbase + row * 784 + off);
                }
            }
            CP_COMMIT();
        }

        uint32_t Ah[8][4];
        epilogue_hidden(D, b1s, q, Ah);

        // ---- layers 2 and 3 ----
        #pragma unroll
        for (int L = 0; L < 2; L++) {
            const char* Ws = (L == 0) ? w2p : w3p;
            const float* bs = (L == 0) ? b2s : b3s;
            #pragma unroll
            for (int f = 0; f < 16; f++)
                #pragma unroll
                for (int j = 0; j < 4; j++) D[f][j] = 0.f;
            #pragma unroll
            for (int kk = 0; kk < 8; kk++) {
                #pragma unroll
                for (int ng = 0; ng < 4; ng++) {
                    uint4 w = *(const uint4*)(Ws + (((kk * 4 + ng) << 9)));
                    uint32_t bw0[2] = { __byte_perm(w.x, 0, 0x1404), __byte_perm(w.x, 0, 0x3424) };
                    uint32_t bw1[2] = { __byte_perm(w.y, 0, 0x1404), __byte_perm(w.y, 0, 0x3424) };
                    uint32_t bw2[2] = { __byte_perm(w.z, 0, 0x1404), __byte_perm(w.z, 0, 0x3424) };
                    uint32_t bw3[2] = { __byte_perm(w.w, 0, 0x1404), __byte_perm(w.w, 0, 0x3424) };
                    mma16816(D[ng * 4 + 0], Ah[kk], bw0);
                    mma16816(D[ng * 4 + 1], Ah[kk], bw1);
                    mma16816(D[ng * 4 + 2], Ah[kk], bw2);
                    mma16816(D[ng * 4 + 3], Ah[kk], bw3);
                }
            }
            epilogue_hidden(D, bs, q, Ah);
        }

        // ---- layer 4 (head; W4 = hi + lo fp16) ----
        float D4[2][4];
        #pragma unroll
        for (int f = 0; f < 2; f++)
            #pragma unroll
            for (int j = 0; j < 4; j++) D4[f][j] = 0.f;
        #pragma unroll
        for (int kk = 0; kk < 8; kk++) {
            #pragma unroll
            for (int n = 0; n < 2; n++) {
                int ofs = ((kk * 16 + n * 8 + r) << 5) + q * 8;
                uint2 bhw = *(const uint2*)(smem + SM_W4HF + ofs);
                uint2 blw = *(const uint2*)(smem + SM_W4LF + ofs);
                uint32_t bh[2] = { bhw.x, bhw.y };
                uint32_t bl[2] = { blw.x, blw.y };
                mma16816(D4[n], Ah[kk], bh);
                mma16816(D4[n], Ah[kk], bl);
            }
        }

        // ---- output ----
        {
            const size_t row0 = (size_t)c * 16 + r;
            float* o0 = out + row0 * DOUT;
            float* o8 = o0 + (size_t)8 * DOUT;
            int cc = q * 2;
            float2 bb = *(const float2*)(b4s + cc);
            *(float2*)(o0 + cc) = make_float2(D4[0][0] + bb.x, D4[0][1] + bb.y);
            *(float2*)(o8 + cc) = make_float2(D4[0][2] + bb.x, D4[0][3] + bb.y);
            if (q == 0) {
                float2 b8 = *(const float2*)(b4s + 8);
                *(float2*)(o0 + 8) = make_float2(D4[1][0] + b8.x, D4[1][1] + b8.y);
                *(float2*)(o8 + 8) = make_float2(D4[1][2] + b8.x, D4[1][3] + b8.y);
            }
        }
    }
}

extern "C" void kernel_launch(void* const* d_in, const int* in_sizes, int n_in,
                              void* d_out, int out_size) {
    const float* x  = (const float*)d_in[0];
    const float* W1 = (const float*)d_in[1];
    const float* b1 = (const float*)d_in[2];
    const float* W2 = (const float*)d_in[3];
    const float* b2 = (const float*)d_in[4];
    const float* W3 = (const float*)d_in[5];
    const float* b3 = (const float*)d_in[6];
    const float* W4 = (const float*)d_in[7];
    const float* b4 = (const float*)d_in[8];
    float* out = (float*)d_out;

    int B = in_sizes[0] / DIN;
    int n_chunks = B / 16;

    static int configured = 0;
    if (!configured) {
        cudaFuncSetAttribute(bmlp_kernel, cudaFuncAttributeMaxDynamicSharedMemorySize, SM_TOTAL);
        configured = 1;
    }

    int grid = 152;
    int max_grid = (n_chunks + NWARP - 1) / NWARP;
    if (grid > max_grid) grid = max_grid;
    bmlp_kernel<<<grid, CTA_THREADS, SM_TOTAL>>>(x, W1, b1, W2, b2, W3, b3, W4, b4, out, n_chunks);
}